// round 3
// baseline (speedup 1.0000x reference)
#include <cuda_runtime.h>

#define TOK   32768
#define DIN   1024
#define RDIM  128
#define NSLOT 4096
#define MAXK  32

// ---------------- scratch (static device arrays; no allocation) ----------------
__device__ float  g_hidden[TOK * RDIM];            // 16.8 MB
__device__ float4 g_scores_v[TOK * NSLOT / 4];     // 512 MB
__device__ int    g_budget[TOK];
__device__ float4 g_counts_v[NSLOT / 4];
__device__ float  g_aux;

#define g_scores ((float*)g_scores_v)
#define g_counts ((float*)g_counts_v)

// ---------------- reductions ----------------
__device__ __forceinline__ float warpReduceMaxF(float v) {
#pragma unroll
    for (int o = 16; o > 0; o >>= 1) v = fmaxf(v, __shfl_xor_sync(0xffffffffu, v, o));
    return v;
}
__device__ __forceinline__ float warpReduceSumF(float v) {
#pragma unroll
    for (int o = 16; o > 0; o >>= 1) v += __shfl_xor_sync(0xffffffffu, v, o);
    return v;
}

// ---------------- K0: zero counts + aux ----------------
__global__ void k_init() {
    int i = blockIdx.x * blockDim.x + threadIdx.x;
    if (i < NSLOT) g_counts[i] = 0.f;
    if (i == 0)    g_aux = 0.f;
}

// ---------------- K1: hidden = relu(x @ W_h + b_h); budget ----------------
__global__ __launch_bounds__(256) void k_hidden(
    const float* __restrict__ x,  const float* __restrict__ Wc, const float* __restrict__ bc,
    const float* __restrict__ Wh, const float* __restrict__ bh, float* __restrict__ out_b)
{
    __shared__ float Xs[32][132];
    __shared__ float Wsm[32][128];
    __shared__ float Wcs[32];

    const int tid = threadIdx.x;
    const int tx = tid & 15, ty = tid >> 4;
    const int t0 = blockIdx.x * 128;

    float acc[8][8];
#pragma unroll
    for (int j = 0; j < 8; j++) {
        int c = (j < 4) ? tx * 4 + j : 64 + tx * 4 + (j - 4);
        float b = bh[c];
#pragma unroll
        for (int i = 0; i < 8; i++) acc[i][j] = b;
    }
    float cacc = 0.f;

    for (int kt = 0; kt < 32; kt++) {
#pragma unroll
        for (int i = 0; i < 4; i++) {
            int id = tid + i * 256;
            int token = id >> 3, kg = id & 7;
            float4 f = *(const float4*)(x + (size_t)(t0 + token) * DIN + kt * 32 + kg * 4);
            Xs[kg * 4 + 0][token] = f.x; Xs[kg * 4 + 1][token] = f.y;
            Xs[kg * 4 + 2][token] = f.z; Xs[kg * 4 + 3][token] = f.w;
        }
#pragma unroll
        for (int i = 0; i < 4; i++) {
            int id = tid + i * 256;
            int rowk = id >> 5, ng = id & 31;
            *(float4*)&Wsm[rowk][ng * 4] =
                *(const float4*)(Wh + (size_t)(kt * 32 + rowk) * RDIM + ng * 4);
        }
        if (tid < 32) Wcs[tid] = Wc[kt * 32 + tid];
        __syncthreads();

#pragma unroll
        for (int k = 0; k < 32; k++) {
            float4 a0 = *(float4*)&Xs[k][ty * 4];
            float4 a1 = *(float4*)&Xs[k][64 + ty * 4];
            float4 b0 = *(float4*)&Wsm[k][tx * 4];
            float4 b1 = *(float4*)&Wsm[k][64 + tx * 4];
            float xf[8] = {a0.x, a0.y, a0.z, a0.w, a1.x, a1.y, a1.z, a1.w};
            float wf[8] = {b0.x, b0.y, b0.z, b0.w, b1.x, b1.y, b1.z, b1.w};
#pragma unroll
            for (int i = 0; i < 8; i++)
#pragma unroll
                for (int j = 0; j < 8; j++)
                    acc[i][j] += xf[i] * wf[j];
        }
        if (tid < 128) {
            float s = 0.f;
#pragma unroll
            for (int k = 0; k < 32; k++) s += Xs[k][tid] * Wcs[k];
            cacc += s;
        }
        __syncthreads();
    }

#pragma unroll
    for (int i = 0; i < 8; i++) {
        int r = (i < 4) ? ty * 4 + i : 64 + ty * 4 + (i - 4);
        float4 o0 = make_float4(fmaxf(acc[i][0], 0.f), fmaxf(acc[i][1], 0.f),
                                fmaxf(acc[i][2], 0.f), fmaxf(acc[i][3], 0.f));
        float4 o1 = make_float4(fmaxf(acc[i][4], 0.f), fmaxf(acc[i][5], 0.f),
                                fmaxf(acc[i][6], 0.f), fmaxf(acc[i][7], 0.f));
        *(float4*)(g_hidden + (size_t)(t0 + r) * RDIM + tx * 4) = o0;
        *(float4*)(g_hidden + (size_t)(t0 + r) * RDIM + 64 + tx * 4) = o1;
    }
    if (tid < 128) {
        float zc = cacc + bc[0];
        float c = 1.f / (1.f + expf(-zc));
        float bf = 4.f + 28.f * c * c;
        int b = (int)floorf(bf);
        g_budget[t0 + tid] = b;
        out_b[t0 + tid] = (float)b;
    }
}

// ---------------- K2: fused scores GEMM + streaming per-token top-32 ----------------
// 128 tokens/block; per N-tile: GEMM -> gmem write -> smem tile -> filter into
// per-token top-32 list; epilogue: bitonic sort, budget softmax, counts.
__global__ __launch_bounds__(256) void k_scores_topk(
    const float* __restrict__ Wsg, const float* __restrict__ bs,
    float* __restrict__ out_idx, float* __restrict__ out_w)
{
    extern __shared__ float sm[];
    float* Hs = sm;                                  // [128][132] transposed hidden
    float* Wt = sm + 128 * 132;                      // [128][132] W tile / score tile (stride 129)
    unsigned long long* topL =
        (unsigned long long*)(sm + 2 * 128 * 132);   // [128][32] packed top lists

    const int tid = threadIdx.x;
    const int tx = tid & 15, ty = tid >> 4;
    const int t0 = blockIdx.x * 128;

#pragma unroll
    for (int i = 0; i < 16; i++) {
        int id = tid + i * 256;
        int token = id >> 5, kg = id & 31;
        float4 f = *(const float4*)(g_hidden + (size_t)(t0 + token) * RDIM + kg * 4);
        Hs[(kg * 4 + 0) * 132 + token] = f.x;
        Hs[(kg * 4 + 1) * 132 + token] = f.y;
        Hs[(kg * 4 + 2) * 132 + token] = f.z;
        Hs[(kg * 4 + 3) * 132 + token] = f.w;
    }
    if (tid < 128) {
#pragma unroll
        for (int j = 0; j < 32; j++) topL[tid * 32 + j] = 0ull;
    }
    unsigned long long myMin = 0ull;   // min of my token's current list
    int minSlot = 0;

    for (int nt = 0; nt < 32; nt++) {
        __syncthreads();   // prior filter reads of Wt done
#pragma unroll
        for (int i = 0; i < 16; i++) {
            int id = tid + i * 256;
            int rowk = id >> 5, ng = id & 31;
            *(float4*)&Wt[rowk * 132 + ng * 4] =
                *(const float4*)(Wsg + (size_t)rowk * NSLOT + nt * 128 + ng * 4);
        }
        __syncthreads();

        float acc[8][8];
#pragma unroll
        for (int j = 0; j < 8; j++) {
            int c = (j < 4) ? tx * 4 + j : 64 + tx * 4 + (j - 4);
            float b = bs[nt * 128 + c];
#pragma unroll
            for (int i = 0; i < 8; i++) acc[i][j] = b;
        }
#pragma unroll 8
        for (int k = 0; k < 128; k++) {
            float4 a0 = *(float4*)&Hs[k * 132 + ty * 4];
            float4 a1 = *(float4*)&Hs[k * 132 + 64 + ty * 4];
            float4 b0 = *(float4*)&Wt[k * 132 + tx * 4];
            float4 b1 = *(float4*)&Wt[k * 132 + 64 + tx * 4];
            float xf[8] = {a0.x, a0.y, a0.z, a0.w, a1.x, a1.y, a1.z, a1.w};
            float wf[8] = {b0.x, b0.y, b0.z, b0.w, b1.x, b1.y, b1.z, b1.w};
#pragma unroll
            for (int i = 0; i < 8; i++)
#pragma unroll
                for (int j = 0; j < 8; j++)
                    acc[i][j] += xf[i] * wf[j];
        }
        // write scores to gmem (coalesced)
#pragma unroll
        for (int i = 0; i < 8; i++) {
            int r = (i < 4) ? ty * 4 + i : 64 + ty * 4 + (i - 4);
            float* base = g_scores + (size_t)(t0 + r) * NSLOT + nt * 128;
            *(float4*)(base + tx * 4)      = make_float4(acc[i][0], acc[i][1], acc[i][2], acc[i][3]);
            *(float4*)(base + 64 + tx * 4) = make_float4(acc[i][4], acc[i][5], acc[i][6], acc[i][7]);
        }
        __syncthreads();   // all GEMM reads of Wt done -> safe to overwrite
        // stash tile into Wt region, stride 129 (conflict-free row reads)
#pragma unroll
        for (int i = 0; i < 8; i++) {
            int r = (i < 4) ? ty * 4 + i : 64 + ty * 4 + (i - 4);
#pragma unroll
            for (int j = 0; j < 4; j++) {
                Wt[r * 129 + tx * 4 + j]      = acc[i][j];
                Wt[r * 129 + 64 + tx * 4 + j] = acc[i][4 + j];
            }
        }
        __syncthreads();
        // filter: one thread per token scans 128 scores
        if (tid < 128) {
            const float* srow = Wt + tid * 129;
            unsigned long long* lst = topL + tid * 32;
            const int nbase = nt * 128;
            for (int c = 0; c < 128; c++) {
                float s = srow[c];
                unsigned b = __float_as_uint(s);
                unsigned k = b ^ ((unsigned)((int)b >> 31) | 0x80000000u);
                unsigned long long packed =
                    ((unsigned long long)k << 12) | (unsigned)(4095 - (nbase + c));
                if (packed > myMin) {
                    lst[minSlot] = packed;
                    unsigned long long mn = lst[0];
                    int ms = 0;
                    for (int q = 1; q < 32; q++) {
                        unsigned long long v = lst[q];
                        if (v < mn) { mn = v; ms = q; }
                    }
                    myMin = mn; minSlot = ms;
                }
            }
        }
    }
    __syncthreads();

    // epilogue: 8 warps x 16 tokens — sort, weights, outputs, counts
    const int lane = tid & 31, wid = tid >> 5;
    for (int it = 0; it < 16; it++) {
        const int t = wid * 16 + it;
        unsigned long long kk = topL[t * 32 + lane];
#pragma unroll
        for (int k2 = 2; k2 <= 32; k2 <<= 1) {
#pragma unroll
            for (int j = k2 >> 1; j > 0; j >>= 1) {
                unsigned long long o = __shfl_xor_sync(0xffffffffu, kk, j);
                bool up = ((lane & k2) == 0);
                bool low = ((lane & j) == 0);
                unsigned long long mx = (kk > o) ? kk : o;
                unsigned long long mn = (kk > o) ? o : kk;
                kk = (up == low) ? mx : mn;   // descending
            }
        }
        unsigned keyv = (unsigned)(kk >> 12);
        unsigned idxv = 4095u - (unsigned)(kk & 0xFFFull);
        unsigned fb = (keyv & 0x80000000u) ? (keyv ^ 0x80000000u) : ~keyv;
        float val = __uint_as_float(fb);

        int b = g_budget[t0 + t];
        float v0 = __shfl_sync(0xffffffffu, val, 0);
        bool msk = lane < b;
        float ev = msk ? __expf(val - v0) : 0.f;
        float zz = warpReduceSumF(ev);
        float w = msk ? ev / zz : 0.f;

        out_idx[(size_t)(t0 + t) * MAXK + lane] = (float)idxv;
        out_w[(size_t)(t0 + t) * MAXK + lane] = w;
        if (msk) atomicAdd(&g_counts[idxv], 1.0f);
    }
}

// ---------------- K3: aux = (N/T^2) * sum_t (sum_n e_tn*counts_n) / (sum_n e_tn) ----------------
__global__ __launch_bounds__(256) void k_aux()
{
    __shared__ float sredZ[8], sredD[8], s_m;
    const int t = blockIdx.x;
    const int tid = threadIdx.x, lane = tid & 31, wid = tid >> 5;
    const float* row = g_scores + (size_t)t * NSLOT;

    float4 r[4];
#pragma unroll
    for (int i = 0; i < 4; i++) r[i] = *(const float4*)(row + (size_t)(tid + i * 256) * 4);

    float m = r[0].x;
#pragma unroll
    for (int i = 0; i < 4; i++) {
        m = fmaxf(m, r[i].x); m = fmaxf(m, r[i].y);
        m = fmaxf(m, r[i].z); m = fmaxf(m, r[i].w);
    }
    m = warpReduceMaxF(m);
    if (lane == 0) sredZ[wid] = m;
    __syncthreads();
    if (tid == 0) {
        float mm = sredZ[0];
#pragma unroll
        for (int i = 1; i < 8; i++) mm = fmaxf(mm, sredZ[i]);
        s_m = mm;
    }
    __syncthreads();
    m = s_m;

    float z = 0.f, d = 0.f;
#pragma unroll
    for (int i = 0; i < 4; i++) {
        float4 c = g_counts_v[tid + i * 256];
        float e0 = __expf(r[i].x - m), e1 = __expf(r[i].y - m);
        float e2 = __expf(r[i].z - m), e3 = __expf(r[i].w - m);
        z += e0 + e1 + e2 + e3;
        d += e0 * c.x + e1 * c.y + e2 * c.z + e3 * c.w;
    }
    z = warpReduceSumF(z);
    d = warpReduceSumF(d);
    if (lane == 0) { sredZ[wid] = z; sredD[wid] = d; }
    __syncthreads();
    if (tid == 0) {
        float zz = 0.f, dd = 0.f;
#pragma unroll
        for (int i = 0; i < 8; i++) { zz += sredZ[i]; dd += sredD[i]; }
        float contrib = (dd / zz) * ((float)NSLOT / ((float)TOK * (float)TOK));
        atomicAdd(&g_aux, contrib);
    }
}

// ---------------- K4: publish aux ----------------
__global__ void k_finish(float* __restrict__ out_aux)
{
    if (threadIdx.x == 0) out_aux[0] = g_aux;
}

// ---------------- launch ----------------
extern "C" void kernel_launch(void* const* d_in, const int* in_sizes, int n_in,
                              void* d_out, int out_size)
{
    const float* x  = (const float*)d_in[0];
    const float* Wc = (const float*)d_in[1];
    const float* bc = (const float*)d_in[2];
    const float* Wh = (const float*)d_in[3];
    const float* bh = (const float*)d_in[4];
    const float* Ws = (const float*)d_in[5];
    const float* bs = (const float*)d_in[6];

    float* out     = (float*)d_out;
    float* out_idx = out;
    float* out_w   = out + TOK * MAXK;
    float* out_b   = out + 2 * TOK * MAXK;
    float* out_aux = out + 2 * TOK * MAXK + TOK;

    const int smem2 = 2 * 128 * 132 * (int)sizeof(float) + 128 * 32 * (int)sizeof(unsigned long long);
    cudaFuncSetAttribute(k_scores_topk, cudaFuncAttributeMaxDynamicSharedMemorySize, smem2);

    k_init<<<(NSLOT + 255) / 256, 256>>>();
    k_hidden<<<TOK / 128, 256>>>(x, Wc, bc, Wh, bh, out_b);
    k_scores_topk<<<TOK / 128, 256, smem2>>>(Ws, bs, out_idx, out_w);
    k_aux<<<TOK, 256>>>();
    k_finish<<<1, 32>>>(out_aux);
}

// round 4
// speedup vs baseline: 1.6705x; 1.6705x over previous
#include <cuda_runtime.h>

#define TOK   32768
#define DIN   1024
#define RDIM  128
#define NSLOT 4096
#define MAXK  32

typedef unsigned long long u64;

// ---------------- scratch ----------------
__device__ float  g_hidden[TOK * RDIM];
__device__ float4 g_scores_v[TOK * NSLOT / 4];     // 512 MB
__device__ int    g_budget[TOK];
__device__ float4 g_counts_v[NSLOT / 4];
__device__ float  g_aux;

#define g_scores ((float*)g_scores_v)
#define g_counts ((float*)g_counts_v)

// ---------------- reductions ----------------
__device__ __forceinline__ float warpReduceMaxF(float v) {
#pragma unroll
    for (int o = 16; o > 0; o >>= 1) v = fmaxf(v, __shfl_xor_sync(0xffffffffu, v, o));
    return v;
}
__device__ __forceinline__ float warpReduceSumF(float v) {
#pragma unroll
    for (int o = 16; o > 0; o >>= 1) v += __shfl_xor_sync(0xffffffffu, v, o);
    return v;
}
__device__ __forceinline__ u64 warpReduceMaxU64(u64 v) {
#pragma unroll
    for (int o = 16; o > 0; o >>= 1) {
        u64 t = __shfl_xor_sync(0xffffffffu, v, o);
        v = (t > v) ? t : v;
    }
    return v;
}

// ---------------- K0 ----------------
__global__ void k_init() {
    int i = blockIdx.x * blockDim.x + threadIdx.x;
    if (i < NSLOT) g_counts[i] = 0.f;
    if (i == 0)    g_aux = 0.f;
}

// ---------------- K1: hidden GEMM + budget (R1 version) ----------------
__global__ __launch_bounds__(256) void k_hidden(
    const float* __restrict__ x,  const float* __restrict__ Wc, const float* __restrict__ bc,
    const float* __restrict__ Wh, const float* __restrict__ bh, float* __restrict__ out_b)
{
    __shared__ float Xs[32][132];
    __shared__ float Wsm[32][128];
    __shared__ float Wcs[32];

    const int tid = threadIdx.x;
    const int tx = tid & 15, ty = tid >> 4;
    const int t0 = blockIdx.x * 128;

    float acc[8][8];
#pragma unroll
    for (int j = 0; j < 8; j++) {
        int c = (j < 4) ? tx * 4 + j : 64 + tx * 4 + (j - 4);
        float b = bh[c];
#pragma unroll
        for (int i = 0; i < 8; i++) acc[i][j] = b;
    }
    float cacc = 0.f;

    for (int kt = 0; kt < 32; kt++) {
#pragma unroll
        for (int i = 0; i < 4; i++) {
            int id = tid + i * 256;
            int token = id >> 3, kg = id & 7;
            float4 f = *(const float4*)(x + (size_t)(t0 + token) * DIN + kt * 32 + kg * 4);
            Xs[kg * 4 + 0][token] = f.x; Xs[kg * 4 + 1][token] = f.y;
            Xs[kg * 4 + 2][token] = f.z; Xs[kg * 4 + 3][token] = f.w;
        }
#pragma unroll
        for (int i = 0; i < 4; i++) {
            int id = tid + i * 256;
            int rowk = id >> 5, ng = id & 31;
            *(float4*)&Wsm[rowk][ng * 4] =
                *(const float4*)(Wh + (size_t)(kt * 32 + rowk) * RDIM + ng * 4);
        }
        if (tid < 32) Wcs[tid] = Wc[kt * 32 + tid];
        __syncthreads();

#pragma unroll
        for (int k = 0; k < 32; k++) {
            float4 a0 = *(float4*)&Xs[k][ty * 4];
            float4 a1 = *(float4*)&Xs[k][64 + ty * 4];
            float4 b0 = *(float4*)&Wsm[k][tx * 4];
            float4 b1 = *(float4*)&Wsm[k][64 + tx * 4];
            float xf[8] = {a0.x, a0.y, a0.z, a0.w, a1.x, a1.y, a1.z, a1.w};
            float wf[8] = {b0.x, b0.y, b0.z, b0.w, b1.x, b1.y, b1.z, b1.w};
#pragma unroll
            for (int i = 0; i < 8; i++)
#pragma unroll
                for (int j = 0; j < 8; j++)
                    acc[i][j] += xf[i] * wf[j];
        }
        if (tid < 128) {
            float s = 0.f;
#pragma unroll
            for (int k = 0; k < 32; k++) s += Xs[k][tid] * Wcs[k];
            cacc += s;
        }
        __syncthreads();
    }

#pragma unroll
    for (int i = 0; i < 8; i++) {
        int r = (i < 4) ? ty * 4 + i : 64 + ty * 4 + (i - 4);
        float4 o0 = make_float4(fmaxf(acc[i][0], 0.f), fmaxf(acc[i][1], 0.f),
                                fmaxf(acc[i][2], 0.f), fmaxf(acc[i][3], 0.f));
        float4 o1 = make_float4(fmaxf(acc[i][4], 0.f), fmaxf(acc[i][5], 0.f),
                                fmaxf(acc[i][6], 0.f), fmaxf(acc[i][7], 0.f));
        *(float4*)(g_hidden + (size_t)(t0 + r) * RDIM + tx * 4) = o0;
        *(float4*)(g_hidden + (size_t)(t0 + r) * RDIM + 64 + tx * 4) = o1;
    }
    if (tid < 128) {
        float zc = cacc + bc[0];
        float c = 1.f / (1.f + expf(-zc));
        float bf = 4.f + 28.f * c * c;
        int b = (int)floorf(bf);
        g_budget[t0 + tid] = b;
        out_b[t0 + tid] = (float)b;
    }
}

// ---------------- K2: scores GEMM (R1 version) ----------------
__global__ __launch_bounds__(256) void k_scores(const float* __restrict__ Wsg,
                                                const float* __restrict__ bs)
{
    extern __shared__ float sm[];
    float* Hs = sm;
    float* Wt = sm + 128 * 132;

    const int tid = threadIdx.x;
    const int tx = tid & 15, ty = tid >> 4;
    const int t0 = blockIdx.x * 128;

#pragma unroll
    for (int i = 0; i < 16; i++) {
        int id = tid + i * 256;
        int token = id >> 5, kg = id & 31;
        float4 f = *(const float4*)(g_hidden + (size_t)(t0 + token) * RDIM + kg * 4);
        Hs[(kg * 4 + 0) * 132 + token] = f.x;
        Hs[(kg * 4 + 1) * 132 + token] = f.y;
        Hs[(kg * 4 + 2) * 132 + token] = f.z;
        Hs[(kg * 4 + 3) * 132 + token] = f.w;
    }

    for (int nt = 0; nt < 32; nt++) {
        __syncthreads();
#pragma unroll
        for (int i = 0; i < 16; i++) {
            int id = tid + i * 256;
            int rowk = id >> 5, ng = id & 31;
            *(float4*)&Wt[rowk * 132 + ng * 4] =
                *(const float4*)(Wsg + (size_t)rowk * NSLOT + nt * 128 + ng * 4);
        }
        __syncthreads();

        float acc[8][8];
#pragma unroll
        for (int j = 0; j < 8; j++) {
            int c = (j < 4) ? tx * 4 + j : 64 + tx * 4 + (j - 4);
            float b = bs[nt * 128 + c];
#pragma unroll
            for (int i = 0; i < 8; i++) acc[i][j] = b;
        }
#pragma unroll 8
        for (int k = 0; k < 128; k++) {
            float4 a0 = *(float4*)&Hs[k * 132 + ty * 4];
            float4 a1 = *(float4*)&Hs[k * 132 + 64 + ty * 4];
            float4 b0 = *(float4*)&Wt[k * 132 + tx * 4];
            float4 b1 = *(float4*)&Wt[k * 132 + 64 + tx * 4];
            float xf[8] = {a0.x, a0.y, a0.z, a0.w, a1.x, a1.y, a1.z, a1.w};
            float wf[8] = {b0.x, b0.y, b0.z, b0.w, b1.x, b1.y, b1.z, b1.w};
#pragma unroll
            for (int i = 0; i < 8; i++)
#pragma unroll
                for (int j = 0; j < 8; j++)
                    acc[i][j] += xf[i] * wf[j];
        }
#pragma unroll
        for (int i = 0; i < 8; i++) {
            int r = (i < 4) ? ty * 4 + i : 64 + ty * 4 + (i - 4);
            float* base = g_scores + (size_t)(t0 + r) * NSLOT + nt * 128;
            *(float4*)(base + tx * 4)      = make_float4(acc[i][0], acc[i][1], acc[i][2], acc[i][3]);
            *(float4*)(base + 64 + tx * 4) = make_float4(acc[i][4], acc[i][5], acc[i][6], acc[i][7]);
        }
    }
}

// ---------------- K3: warp-per-token exact top-32 ----------------
// Row in registers (128 keys/lane). Statistical threshold -> ballot compaction
// -> exact merge-extraction. Exact register fallback for any distribution.
__global__ __launch_bounds__(256, 1) void k_topk(float* __restrict__ out_idx,
                                                 float* __restrict__ out_w)
{
    __shared__ u64 cand[8][256];

    const int tid = threadIdx.x, lane = tid & 31, wid = tid >> 5;
    const int t = blockIdx.x * 8 + wid;
    const float* row = g_scores + (size_t)t * NSLOT;

    // load 128 values/lane; element index of key[c*4+j] = c*128 + lane*4 + j
    unsigned key[128];
    float s = 0.f, s2 = 0.f;
#pragma unroll
    for (int c = 0; c < 32; c++) {
        float4 f = *(const float4*)(row + (size_t)(c * 32 + lane) * 4);
        float vv[4] = {f.x, f.y, f.z, f.w};
#pragma unroll
        for (int j = 0; j < 4; j++) {
            s += vv[j]; s2 += vv[j] * vv[j];
            unsigned b = __float_as_uint(vv[j]);
            key[c * 4 + j] = b ^ ((unsigned)((int)b >> 31) | 0x80000000u);
        }
    }
    s = warpReduceSumF(s);
    s2 = warpReduceSumF(s2);
    const float mean = s * (1.f / NSLOT);
    const float var = fmaxf(s2 * (1.f / NSLOT) - mean * mean, 0.f);
    const float sigma = sqrtf(var) + 1e-20f;

    // threshold attempts
    float zf = 2.2f;
    int cnt = 0;
    bool ok = false;
    for (int attempt = 0; attempt < 10; attempt++) {
        float thr = mean + zf * sigma;
        unsigned tb = __float_as_uint(thr);
        unsigned thrKey = tb ^ ((unsigned)((int)tb >> 31) | 0x80000000u);
        int base = 0;
#pragma unroll
        for (int i = 0; i < 128; i++) {
            bool c = key[i] > thrKey;
            unsigned mask = __ballot_sync(0xffffffffu, c);
            if (c) {
                int pos = base + __popc(mask & ((1u << lane) - 1u));
                if (pos < 256) {
                    unsigned idx = (unsigned)((i >> 2) * 128 + lane * 4 + (i & 3));
                    cand[wid][pos] = ((u64)key[i] << 12) | (u64)(4095u - idx);
                }
            }
            base += __popc(mask);
        }
        cnt = base;
        if (cnt >= MAXK && cnt <= 256) { ok = true; break; }
        if (cnt < MAXK) zf -= 0.6f; else zf += 0.45f;
    }

    u64 mysel = 0;
    if (ok) {
        // each lane owns slots lane+32q, q<8 ; presort desc; 32 merge rounds
        u64 cl[8];
#pragma unroll
        for (int q = 0; q < 8; q++) {
            int p = lane + 32 * q;
            cl[q] = (p < cnt) ? cand[wid][p] : 0ull;
        }
        // sort 8 desc (insertion network, static indices)
#pragma unroll
        for (int a = 1; a < 8; a++)
#pragma unroll
            for (int b2 = a; b2 > 0; b2--) {
                u64 lo = cl[b2 - 1] < cl[b2] ? cl[b2 - 1] : cl[b2];
                u64 hi = cl[b2 - 1] < cl[b2] ? cl[b2] : cl[b2 - 1];
                cl[b2 - 1] = hi; cl[b2] = lo;
            }
#pragma unroll
        for (int r2 = 0; r2 < MAXK; r2++) {
            u64 wb = warpReduceMaxU64(cl[0]);
            bool win = (cl[0] == wb);
            // winner shifts left (uniqueness of packed idx -> exactly one winner)
            if (win) {
#pragma unroll
                for (int q = 0; q < 7; q++) cl[q] = cl[q + 1];
                cl[7] = 0ull;
            }
            if (lane == r2) mysel = wb;
        }
    } else {
        // exact fallback: iterative extraction over register data
        for (int r2 = 0; r2 < MAXK; r2++) {
            u64 lb = 0;
#pragma unroll
            for (int i = 0; i < 128; i++) {
                unsigned idx = (unsigned)((i >> 2) * 128 + lane * 4 + (i & 3));
                u64 p = ((u64)key[i] << 12) | (u64)(4095u - idx);
                if (p > lb) lb = p;
            }
            u64 wb = warpReduceMaxU64(lb);
            if (lb == wb && wb != 0ull) {
#pragma unroll
                for (int i = 0; i < 128; i++) {
                    unsigned idx = (unsigned)((i >> 2) * 128 + lane * 4 + (i & 3));
                    u64 p = ((u64)key[i] << 12) | (u64)(4095u - idx);
                    if (p == wb) key[i] = 0u;
                }
            }
            if (lane == r2) mysel = wb;
        }
    }

    // unpack lane's selection (lane = rank)
    unsigned keyv = (unsigned)(mysel >> 12);
    unsigned idxv = 4095u - (unsigned)(mysel & 0xFFFull);
    unsigned fb = (keyv & 0x80000000u) ? (keyv ^ 0x80000000u) : ~keyv;
    float val = __uint_as_float(fb);

    int b = g_budget[t];
    float v0 = __shfl_sync(0xffffffffu, val, 0);
    bool msk = lane < b;
    float ev = msk ? __expf(val - v0) : 0.f;
    float zz = warpReduceSumF(ev);
    float w = msk ? ev / zz : 0.f;

    out_idx[(size_t)t * MAXK + lane] = (float)idxv;
    out_w[(size_t)t * MAXK + lane] = w;
    if (msk) atomicAdd(&g_counts[idxv], 1.0f);
}

// ---------------- K4: aux ----------------
__global__ __launch_bounds__(256) void k_aux()
{
    __shared__ float sredZ[8], sredD[8], s_m;
    const int t = blockIdx.x;
    const int tid = threadIdx.x, lane = tid & 31, wid = tid >> 5;
    const float* row = g_scores + (size_t)t * NSLOT;

    float4 r[4];
#pragma unroll
    for (int i = 0; i < 4; i++) r[i] = *(const float4*)(row + (size_t)(tid + i * 256) * 4);

    float m = r[0].x;
#pragma unroll
    for (int i = 0; i < 4; i++) {
        m = fmaxf(m, r[i].x); m = fmaxf(m, r[i].y);
        m = fmaxf(m, r[i].z); m = fmaxf(m, r[i].w);
    }
    m = warpReduceMaxF(m);
    if (lane == 0) sredZ[wid] = m;
    __syncthreads();
    if (tid == 0) {
        float mm = sredZ[0];
#pragma unroll
        for (int i = 1; i < 8; i++) mm = fmaxf(mm, sredZ[i]);
        s_m = mm;
    }
    __syncthreads();
    m = s_m;

    float z = 0.f, d = 0.f;
#pragma unroll
    for (int i = 0; i < 4; i++) {
        float4 c = g_counts_v[tid + i * 256];
        float e0 = __expf(r[i].x - m), e1 = __expf(r[i].y - m);
        float e2 = __expf(r[i].z - m), e3 = __expf(r[i].w - m);
        z += e0 + e1 + e2 + e3;
        d += e0 * c.x + e1 * c.y + e2 * c.z + e3 * c.w;
    }
    z = warpReduceSumF(z);
    d = warpReduceSumF(d);
    if (lane == 0) { sredZ[wid] = z; sredD[wid] = d; }
    __syncthreads();
    if (tid == 0) {
        float zz = 0.f, dd = 0.f;
#pragma unroll
        for (int i = 0; i < 8; i++) { zz += sredZ[i]; dd += sredD[i]; }
        float contrib = (dd / zz) * ((float)NSLOT / ((float)TOK * (float)TOK));
        atomicAdd(&g_aux, contrib);
    }
}

// ---------------- K5 ----------------
__global__ void k_finish(float* __restrict__ out_aux)
{
    if (threadIdx.x == 0) out_aux[0] = g_aux;
}

// ---------------- launch ----------------
extern "C" void kernel_launch(void* const* d_in, const int* in_sizes, int n_in,
                              void* d_out, int out_size)
{
    const float* x  = (const float*)d_in[0];
    const float* Wc = (const float*)d_in[1];
    const float* bc = (const float*)d_in[2];
    const float* Wh = (const float*)d_in[3];
    const float* bh = (const float*)d_in[4];
    const float* Ws = (const float*)d_in[5];
    const float* bs = (const float*)d_in[6];

    float* out     = (float*)d_out;
    float* out_idx = out;
    float* out_w   = out + TOK * MAXK;
    float* out_b   = out + 2 * TOK * MAXK;
    float* out_aux = out + 2 * TOK * MAXK + TOK;

    const int smem2 = 2 * 128 * 132 * (int)sizeof(float);
    cudaFuncSetAttribute(k_scores, cudaFuncAttributeMaxDynamicSharedMemorySize, smem2);

    k_init<<<(NSLOT + 255) / 256, 256>>>();
    k_hidden<<<TOK / 128, 256>>>(x, Wc, bc, Wh, bh, out_b);
    k_scores<<<TOK / 128, 256, smem2>>>(Ws, bs);
    k_topk<<<TOK / 8, 256>>>(out_idx, out_w);
    k_aux<<<TOK, 256>>>();
    k_finish<<<1, 32>>>(out_aux);
}